// round 6
// baseline (speedup 1.0000x reference)
#include <cuda_runtime.h>
#include <cuda_bf16.h>
#include <math.h>

// Problem constants
#define SEQ    2048
#define HID    2048
#define NH     32
#define NOPE   128
#define ROPE_D 64
#define QKD    192          // NOPE + ROPE
#define VD     128
#define KV_RANK 512
#define SWIN   128
#define CKV_W  576          // KV_RANK + ROPE
#define KV_W   8192         // NH * (NOPE + VD)
#define QW     6144         // NH * QKD
#define AOW    4096         // NH * VD
#define NEGINF (-1000000000.0f)
#define ATTN_SCALE 0.07216878364870323f   // 192^-0.5

// ---------------- scratch (device globals; no allocation allowed) ----------------
__device__ float g_q[(size_t)SEQ * QW];        // 50.3 MB  q projection (rope applied in place)
__device__ float g_ckv[(size_t)SEQ * CKV_W];   // 4.7 MB   latent + k_rope raw
__device__ float g_kv[(size_t)SEQ * KV_W];     // 67 MB    expanded k_nope|v per head
__device__ float g_krope[(size_t)SEQ * ROPE_D];// rotated k_rope (shared across heads)
__device__ float g_attn[(size_t)SEQ * AOW];    // 33.5 MB  attention output (s, NH*VD)

// ---------------- tiled fp32 GEMM: C[M,N] = A[M,K]@B[K,N] (+bias) ----------------
// 128x128 block tile, BK=16, 256 threads, 8x8 per-thread microtile.
// Requires: M % 128 == 0, K % 16 == 0, lda/ldb % 4 == 0. N may be ragged (guarded).
__global__ __launch_bounds__(256) void sgemm_bias(
    const float* __restrict__ A, int lda,
    const float* __restrict__ B, int ldb,
    const float* __restrict__ bias,
    float* __restrict__ C, int ldc,
    int M, int N, int K)
{
    __shared__ float As[16][128];   // transposed: As[k][m]
    __shared__ float Bs[16][128];   // Bs[k][n]

    const int tid = threadIdx.x;
    const int bm = blockIdx.y * 128;
    const int bn = blockIdx.x * 128;
    const int tx = tid & 15;        // n-direction
    const int ty = tid >> 4;        // m-direction

    float acc[8][8];
    #pragma unroll
    for (int i = 0; i < 8; i++)
        #pragma unroll
        for (int j = 0; j < 8; j++) acc[i][j] = 0.0f;

    for (int k0 = 0; k0 < K; k0 += 16) {
        // ---- stage A tile: 128 rows x 16 cols = 512 float4, 2 per thread ----
        #pragma unroll
        for (int it = 0; it < 2; it++) {
            int idx = tid + it * 256;          // 0..511
            int row = idx >> 2;                // 0..127
            int c4  = (idx & 3) << 2;          // 0,4,8,12
            float4 v = *reinterpret_cast<const float4*>(
                &A[(size_t)(bm + row) * lda + k0 + c4]);
            As[c4 + 0][row] = v.x;
            As[c4 + 1][row] = v.y;
            As[c4 + 2][row] = v.z;
            As[c4 + 3][row] = v.w;
        }
        // ---- stage B tile: 16 rows x 128 cols = 512 float4, 2 per thread ----
        #pragma unroll
        for (int it = 0; it < 2; it++) {
            int idx = tid + it * 256;
            int row = idx >> 5;                // 0..15
            int c4  = (idx & 31) << 2;         // 0..124
            int col = bn + c4;
            float4 v;
            if (col + 4 <= N) {
                v = *reinterpret_cast<const float4*>(
                    &B[(size_t)(k0 + row) * ldb + col]);
            } else {
                v.x = (col + 0 < N) ? B[(size_t)(k0 + row) * ldb + col + 0] : 0.0f;
                v.y = (col + 1 < N) ? B[(size_t)(k0 + row) * ldb + col + 1] : 0.0f;
                v.z = (col + 2 < N) ? B[(size_t)(k0 + row) * ldb + col + 2] : 0.0f;
                v.w = (col + 3 < N) ? B[(size_t)(k0 + row) * ldb + col + 3] : 0.0f;
            }
            *reinterpret_cast<float4*>(&Bs[row][c4]) = v;
        }
        __syncthreads();

        #pragma unroll
        for (int k = 0; k < 16; k++) {
            float a[8], b[8];
            #pragma unroll
            for (int i = 0; i < 8; i++) a[i] = As[k][ty * 8 + i];
            #pragma unroll
            for (int j = 0; j < 8; j++) b[j] = Bs[k][tx * 8 + j];
            #pragma unroll
            for (int i = 0; i < 8; i++)
                #pragma unroll
                for (int j = 0; j < 8; j++)
                    acc[i][j] = fmaf(a[i], b[j], acc[i][j]);
        }
        __syncthreads();
    }

    // ---- store ----
    #pragma unroll
    for (int i = 0; i < 8; i++) {
        int row = bm + ty * 8 + i;
        #pragma unroll
        for (int j = 0; j < 8; j++) {
            int col = bn + tx * 8 + j;
            if (col < N) {
                float v = acc[i][j];
                if (bias) v += bias[col];
                C[(size_t)row * ldc + col] = v;
            }
        }
    }
}

// ---------------- RoPE on q (in place, last 64 dims of each head) ----------------
__global__ void rope_q_kernel(const float* __restrict__ cosp,
                              const float* __restrict__ sinp)
{
    int idx = blockIdx.x * blockDim.x + threadIdx.x;  // SEQ*NH*32
    int r = idx & 31;
    int h = (idx >> 5) & 31;
    int i = idx >> 10;
    float* base = &g_q[(size_t)i * QW + h * QKD + NOPE];
    float x0 = base[r];
    float x1 = base[r + 32];
    float c0 = cosp[i * ROPE_D + r];
    float c1 = cosp[i * ROPE_D + 32 + r];
    float s0 = sinp[i * ROPE_D + r];
    float s1 = sinp[i * ROPE_D + 32 + r];
    base[r]      = x0 * c0 - x1 * s0;   // x*cos + (-x_hi)*sin
    base[r + 32] = x1 * c1 + x0 * s1;   // x*cos + ( x_lo)*sin
}

// ---------------- RoPE on k_rope (from ckv tail -> g_krope) ----------------
__global__ void rope_k_kernel(const float* __restrict__ cosp,
                              const float* __restrict__ sinp)
{
    int idx = blockIdx.x * blockDim.x + threadIdx.x;  // SEQ*32
    int r = idx & 31;
    int i = idx >> 5;
    const float* base = &g_ckv[(size_t)i * CKV_W + KV_RANK];
    float x0 = base[r];
    float x1 = base[r + 32];
    float c0 = cosp[i * ROPE_D + r];
    float c1 = cosp[i * ROPE_D + 32 + r];
    float s0 = sinp[i * ROPE_D + r];
    float s1 = sinp[i * ROPE_D + 32 + r];
    g_krope[(size_t)i * ROPE_D + r]      = x0 * c0 - x1 * s0;
    g_krope[(size_t)i * ROPE_D + 32 + r] = x1 * c1 + x0 * s1;
}

// ---------------- sliding-window attention with sink ----------------
// grid (SEQ, NH), 128 threads. Thread t = key slot (query phase) then dim d (output phase).
__global__ __launch_bounds__(128) void attn_kernel(const float* __restrict__ sinks)
{
    const int i = blockIdx.x;
    const int h = blockIdx.y;
    const int t = threadIdx.x;   // 0..127

    __shared__ float qs[QKD];
    __shared__ float red[128];
    __shared__ float ps[128];

    const float* qp = &g_q[(size_t)i * QW + h * QKD];
    if (t < 128)       qs[t]       = qp[t];
    if (t + 128 < QKD) qs[t + 128] = qp[t + 128];
    __syncthreads();

    // key index for this thread: j in [i-127, i]
    const int j = i - 127 + t;
    float l = NEGINF;
    if (j >= 0) {
        const float* kp = &g_kv[(size_t)j * KV_W + h * 256];      // k_nope
        const float* rp = &g_krope[(size_t)j * ROPE_D];           // rotated k_rope
        float acc = 0.0f;
        #pragma unroll 8
        for (int d = 0; d < NOPE; d++) acc = fmaf(qs[d], kp[d], acc);
        #pragma unroll 8
        for (int d = 0; d < ROPE_D; d++) acc = fmaf(qs[NOPE + d], rp[d], acc);
        l = acc * ATTN_SCALE;
    }

    // max reduction
    red[t] = l;
    __syncthreads();
    #pragma unroll
    for (int s = 64; s > 0; s >>= 1) {
        if (t < s) red[t] = fmaxf(red[t], red[t + s]);
        __syncthreads();
    }
    const float snk = sinks[h];
    const float m = fmaxf(red[0], snk);
    __syncthreads();

    // exp + sum reduction (invalid slots contribute 0)
    float p = (j >= 0) ? __expf(l - m) : 0.0f;
    ps[t] = p;
    red[t] = p;
    __syncthreads();
    #pragma unroll
    for (int s = 64; s > 0; s >>= 1) {
        if (t < s) red[t] += red[t + s];
        __syncthreads();
    }
    const float inv = 1.0f / (red[0] + __expf(snk - m));

    // output phase: thread t = output dim d; coalesced reads of v rows
    const int t0 = (i < 127) ? (127 - i) : 0;
    float acc = 0.0f;
    for (int tt = t0; tt < 128; tt++) {
        int jj = i - 127 + tt;
        acc = fmaf(ps[tt], g_kv[(size_t)jj * KV_W + h * 256 + NOPE + t], acc);
    }
    g_attn[(size_t)i * AOW + h * VD + t] = acc * inv;
}

// ---------------- launch ----------------
extern "C" void kernel_launch(void* const* d_in, const int* in_sizes, int n_in,
                              void* d_out, int out_size)
{
    const float* hidden = (const float*)d_in[0];
    const float* cosp   = (const float*)d_in[1];
    const float* sinp   = (const float*)d_in[2];
    const float* Wq     = (const float*)d_in[3];
    const float* bq     = (const float*)d_in[4];
    const float* Wkva   = (const float*)d_in[5];
    const float* bkva   = (const float*)d_in[6];
    const float* Wkvb   = (const float*)d_in[7];
    const float* Wo     = (const float*)d_in[8];
    const float* bo     = (const float*)d_in[9];
    const float* sinks  = (const float*)d_in[10];
    float* out = (float*)d_out;

    float *q, *ckv, *kv, *attn;
    cudaGetSymbolAddress((void**)&q,    g_q);
    cudaGetSymbolAddress((void**)&ckv,  g_ckv);
    cudaGetSymbolAddress((void**)&kv,   g_kv);
    cudaGetSymbolAddress((void**)&attn, g_attn);

    // 1) q = hidden @ Wq + bq          [2048, 6144] K=2048
    sgemm_bias<<<dim3(QW / 128, SEQ / 128), 256>>>(
        hidden, HID, Wq, QW, bq, q, QW, SEQ, QW, HID);

    // 2) ckv = hidden @ Wkva + bkva    [2048, 576]  K=2048
    sgemm_bias<<<dim3((CKV_W + 127) / 128, SEQ / 128), 256>>>(
        hidden, HID, Wkva, CKV_W, bkva, ckv, CKV_W, SEQ, CKV_W, HID);

    // 3) RoPE on q (in place) and k_rope (-> g_krope)
    rope_q_kernel<<<(SEQ * NH * 32) / 256, 256>>>(cosp, sinp);
    rope_k_kernel<<<(SEQ * 32) / 256, 256>>>(cosp, sinp);

    // 4) kv = ckv[:, :512] @ Wkvb      [2048, 8192] K=512
    sgemm_bias<<<dim3(KV_W / 128, SEQ / 128), 256>>>(
        ckv, CKV_W, Wkvb, KV_W, nullptr, kv, KV_W, SEQ, KV_W, KV_RANK);

    // 5) sliding-window attention with sink
    attn_kernel<<<dim3(SEQ, NH), 128>>>(sinks);

    // 6) out = attn @ Wo + bo          [2048, 2048] K=4096
    sgemm_bias<<<dim3(HID / 128, SEQ / 128), 256>>>(
        attn, AOW, Wo, HID, bo, out, HID, SEQ, HID, AOW);
}

// round 7
// speedup vs baseline: 1.0404x; 1.0404x over previous
#include <cuda_runtime.h>
#include <cuda_bf16.h>
#include <math.h>
#include <stdint.h>

// Problem constants
#define SEQ    2048
#define HID    2048
#define NH     32
#define NOPE   128
#define ROPE_D 64
#define QKD    192          // NOPE + ROPE
#define VD     128
#define KV_RANK 512
#define SWIN   128
#define CKV_W  576          // KV_RANK + ROPE
#define KV_W   8192         // NH * (NOPE + VD)
#define QW     6144         // NH * QKD
#define AOW    4096         // NH * VD
#define NEGINF (-1000000000.0f)
#define ATTN_SCALE 0.07216878364870323f   // 192^-0.5

#define BPAD 24             // smem row stride in halves (48B: 16B-aligned, conflict-free)

// ---------------- scratch (device globals; no allocation allowed) ----------------
__device__ float g_q[(size_t)SEQ * QW];
__device__ float g_ckv[(size_t)SEQ * CKV_W];
__device__ float g_kv[(size_t)SEQ * KV_W];
__device__ float g_krope[(size_t)SEQ * ROPE_D];
__device__ float g_attn[(size_t)SEQ * AOW];

// ---------------- bf16 mma wrapper ----------------
__device__ __forceinline__ void mma16816(float* c, const uint32_t* a, const uint32_t* b)
{
    asm volatile(
        "mma.sync.aligned.m16n8k16.row.col.f32.bf16.bf16.f32 "
        "{%0,%1,%2,%3}, {%4,%5,%6,%7}, {%8,%9}, {%0,%1,%2,%3};\n"
        : "+f"(c[0]), "+f"(c[1]), "+f"(c[2]), "+f"(c[3])
        : "r"(a[0]), "r"(a[1]), "r"(a[2]), "r"(a[3]),
          "r"(b[0]), "r"(b[1]));
}

// ---------------- bf16x3 tensor GEMM: C[M=2048,N] = A[M,K]@B[K,N] (+bias) -------
// Block tile 128x128, BK=16, 256 threads, 8 warps (2m x 4n), warp tile 64x32.
// fp32 operands split into bf16 hi/lo; 3 MMA passes (hi*hi + hi*lo + lo*hi).
// Requires: M % 128 == 0, K % 16 == 0. N may be ragged (guarded).
__global__ __launch_bounds__(256) void gemm_bf16x3(
    const float* __restrict__ A, int lda,
    const float* __restrict__ B, int ldb,
    const float* __restrict__ bias,
    float* __restrict__ C, int ldc,
    int N, int K)
{
    __shared__ __nv_bfloat16 As[2][128 * BPAD];   // [part][m][k]
    __shared__ __nv_bfloat16 Bs[2][128 * BPAD];   // [part][n][k]

    const int tid  = threadIdx.x;
    const int lane = tid & 31;
    const int w    = tid >> 5;
    const int wm   = w >> 2;        // 0..1  (m)
    const int wn   = w & 3;         // 0..3  (n)
    const int bm   = blockIdx.y * 128;
    const int bn   = blockIdx.x * 128;
    const int g    = lane >> 2;     // 0..7
    const int q4   = (lane & 3) * 2;

    float acc[4][4][4];
    #pragma unroll
    for (int mi = 0; mi < 4; mi++)
        #pragma unroll
        for (int ni = 0; ni < 4; ni++)
            #pragma unroll
            for (int e = 0; e < 4; e++) acc[mi][ni][e] = 0.0f;

    const int nk = K / 16;
    float4 ra[2], rb[2];

    // ---- prefetch tile 0 into registers ----
    #pragma unroll
    for (int it = 0; it < 2; it++) {
        int lin  = tid + it * 256;
        int arow = lin >> 2, ac4 = (lin & 3) * 4;
        ra[it] = *reinterpret_cast<const float4*>(&A[(size_t)(bm + arow) * lda + ac4]);
        int krow = lin >> 5, nc4 = (lin & 31) * 4;
        int col  = bn + nc4;
        if (col + 4 <= N) {
            rb[it] = *reinterpret_cast<const float4*>(&B[(size_t)krow * ldb + col]);
        } else {
            rb[it].x = (col + 0 < N) ? B[(size_t)krow * ldb + col + 0] : 0.0f;
            rb[it].y = (col + 1 < N) ? B[(size_t)krow * ldb + col + 1] : 0.0f;
            rb[it].z = (col + 2 < N) ? B[(size_t)krow * ldb + col + 2] : 0.0f;
            rb[it].w = (col + 3 < N) ? B[(size_t)krow * ldb + col + 3] : 0.0f;
        }
    }

    for (int kt = 0; kt < nk; kt++) {
        // ---- write prefetched registers to smem (with bf16 hi/lo split) ----
        #pragma unroll
        for (int it = 0; it < 2; it++) {
            int lin  = tid + it * 256;
            int arow = lin >> 2, ac4 = (lin & 3) * 4;
            float av[4] = {ra[it].x, ra[it].y, ra[it].z, ra[it].w};
            #pragma unroll
            for (int e = 0; e < 4; e++) {
                float x = av[e];
                __nv_bfloat16 hi = __float2bfloat16(x);
                __nv_bfloat16 lo = __float2bfloat16(x - __bfloat162float(hi));
                As[0][arow * BPAD + ac4 + e] = hi;
                As[1][arow * BPAD + ac4 + e] = lo;
            }
            int krow = lin >> 5, nc4 = (lin & 31) * 4;
            float bv[4] = {rb[it].x, rb[it].y, rb[it].z, rb[it].w};
            #pragma unroll
            for (int e = 0; e < 4; e++) {
                float x = bv[e];
                __nv_bfloat16 hi = __float2bfloat16(x);
                __nv_bfloat16 lo = __float2bfloat16(x - __bfloat162float(hi));
                Bs[0][(nc4 + e) * BPAD + krow] = hi;
                Bs[1][(nc4 + e) * BPAD + krow] = lo;
            }
        }
        __syncthreads();

        // ---- prefetch next tile (LDG latency hidden behind MMA compute) ----
        if (kt + 1 < nk) {
            int k0 = (kt + 1) * 16;
            #pragma unroll
            for (int it = 0; it < 2; it++) {
                int lin  = tid + it * 256;
                int arow = lin >> 2, ac4 = (lin & 3) * 4;
                ra[it] = *reinterpret_cast<const float4*>(
                    &A[(size_t)(bm + arow) * lda + k0 + ac4]);
                int krow = lin >> 5, nc4 = (lin & 31) * 4;
                int col  = bn + nc4;
                if (col + 4 <= N) {
                    rb[it] = *reinterpret_cast<const float4*>(
                        &B[(size_t)(k0 + krow) * ldb + col]);
                } else {
                    rb[it].x = (col + 0 < N) ? B[(size_t)(k0 + krow) * ldb + col + 0] : 0.0f;
                    rb[it].y = (col + 1 < N) ? B[(size_t)(k0 + krow) * ldb + col + 1] : 0.0f;
                    rb[it].z = (col + 2 < N) ? B[(size_t)(k0 + krow) * ldb + col + 2] : 0.0f;
                    rb[it].w = (col + 3 < N) ? B[(size_t)(k0 + krow) * ldb + col + 3] : 0.0f;
                }
            }
        }

        // ---- load fragments from smem ----
        uint32_t af[2][4][4];
        uint32_t bf[2][4][2];
        #pragma unroll
        for (int p = 0; p < 2; p++)
            #pragma unroll
            for (int mi = 0; mi < 4; mi++) {
                const __nv_bfloat16* base = &As[p][(wm * 64 + mi * 16 + g) * BPAD + q4];
                af[p][mi][0] = *reinterpret_cast<const uint32_t*>(base);
                af[p][mi][1] = *reinterpret_cast<const uint32_t*>(base + 8 * BPAD);
                af[p][mi][2] = *reinterpret_cast<const uint32_t*>(base + 8);
                af[p][mi][3] = *reinterpret_cast<const uint32_t*>(base + 8 * BPAD + 8);
            }
        #pragma unroll
        for (int p = 0; p < 2; p++)
            #pragma unroll
            for (int ni = 0; ni < 4; ni++) {
                const __nv_bfloat16* base = &Bs[p][(wn * 32 + ni * 8 + g) * BPAD + q4];
                bf[p][ni][0] = *reinterpret_cast<const uint32_t*>(base);
                bf[p][ni][1] = *reinterpret_cast<const uint32_t*>(base + 8);
            }

        // ---- 3-pass compensated MMA ----
        #pragma unroll
        for (int mi = 0; mi < 4; mi++)
            #pragma unroll
            for (int ni = 0; ni < 4; ni++) {
                mma16816(acc[mi][ni], af[0][mi], bf[0][ni]);   // hi*hi
                mma16816(acc[mi][ni], af[0][mi], bf[1][ni]);   // hi*lo
                mma16816(acc[mi][ni], af[1][mi], bf[0][ni]);   // lo*hi
            }
        __syncthreads();
    }

    // ---- store ----
    #pragma unroll
    for (int mi = 0; mi < 4; mi++) {
        int r0 = bm + wm * 64 + mi * 16 + g;
        #pragma unroll
        for (int ni = 0; ni < 4; ni++) {
            int c = bn + wn * 32 + ni * 8 + q4;
            if (c < N) {
                float bb = bias ? bias[c] : 0.0f;
                C[(size_t)r0 * ldc + c]       = acc[mi][ni][0] + bb;
                C[(size_t)(r0 + 8) * ldc + c] = acc[mi][ni][2] + bb;
            }
            if (c + 1 < N) {
                float bb = bias ? bias[c + 1] : 0.0f;
                C[(size_t)r0 * ldc + c + 1]       = acc[mi][ni][1] + bb;
                C[(size_t)(r0 + 8) * ldc + c + 1] = acc[mi][ni][3] + bb;
            }
        }
    }
}

// ---------------- RoPE on q (in place, last 64 dims of each head) ----------------
__global__ void rope_q_kernel(const float* __restrict__ cosp,
                              const float* __restrict__ sinp)
{
    int idx = blockIdx.x * blockDim.x + threadIdx.x;  // SEQ*NH*32
    int r = idx & 31;
    int h = (idx >> 5) & 31;
    int i = idx >> 10;
    float* base = &g_q[(size_t)i * QW + h * QKD + NOPE];
    float x0 = base[r];
    float x1 = base[r + 32];
    float c0 = cosp[i * ROPE_D + r];
    float c1 = cosp[i * ROPE_D + 32 + r];
    float s0 = sinp[i * ROPE_D + r];
    float s1 = sinp[i * ROPE_D + 32 + r];
    base[r]      = x0 * c0 - x1 * s0;
    base[r + 32] = x1 * c1 + x0 * s1;
}

// ---------------- RoPE on k_rope (from ckv tail -> g_krope) ----------------
__global__ void rope_k_kernel(const float* __restrict__ cosp,
                              const float* __restrict__ sinp)
{
    int idx = blockIdx.x * blockDim.x + threadIdx.x;  // SEQ*32
    int r = idx & 31;
    int i = idx >> 5;
    const float* base = &g_ckv[(size_t)i * CKV_W + KV_RANK];
    float x0 = base[r];
    float x1 = base[r + 32];
    float c0 = cosp[i * ROPE_D + r];
    float c1 = cosp[i * ROPE_D + 32 + r];
    float s0 = sinp[i * ROPE_D + r];
    float s1 = sinp[i * ROPE_D + 32 + r];
    g_krope[(size_t)i * ROPE_D + r]      = x0 * c0 - x1 * s0;
    g_krope[(size_t)i * ROPE_D + 32 + r] = x1 * c1 + x0 * s1;
}

// ---------------- sliding-window attention with sink ----------------
__global__ __launch_bounds__(128) void attn_kernel(const float* __restrict__ sinks)
{
    const int i = blockIdx.x;
    const int h = blockIdx.y;
    const int t = threadIdx.x;   // 0..127

    __shared__ float qs[QKD];
    __shared__ float red[128];
    __shared__ float ps[128];

    const float* qp = &g_q[(size_t)i * QW + h * QKD];
    if (t < 128)       qs[t]       = qp[t];
    if (t + 128 < QKD) qs[t + 128] = qp[t + 128];
    __syncthreads();

    const int j = i - 127 + t;
    float l = NEGINF;
    if (j >= 0) {
        const float* kp = &g_kv[(size_t)j * KV_W + h * 256];
        const float* rp = &g_krope[(size_t)j * ROPE_D];
        float acc = 0.0f;
        #pragma unroll 8
        for (int d = 0; d < NOPE; d++) acc = fmaf(qs[d], kp[d], acc);
        #pragma unroll 8
        for (int d = 0; d < ROPE_D; d++) acc = fmaf(qs[NOPE + d], rp[d], acc);
        l = acc * ATTN_SCALE;
    }

    red[t] = l;
    __syncthreads();
    #pragma unroll
    for (int s = 64; s > 0; s >>= 1) {
        if (t < s) red[t] = fmaxf(red[t], red[t + s]);
        __syncthreads();
    }
    const float snk = sinks[h];
    const float m = fmaxf(red[0], snk);
    __syncthreads();

    float p = (j >= 0) ? __expf(l - m) : 0.0f;
    ps[t] = p;
    red[t] = p;
    __syncthreads();
    #pragma unroll
    for (int s = 64; s > 0; s >>= 1) {
        if (t < s) red[t] += red[t + s];
        __syncthreads();
    }
    const float inv = 1.0f / (red[0] + __expf(snk - m));

    const int t0 = (i < 127) ? (127 - i) : 0;
    float acc = 0.0f;
    for (int tt = t0; tt < 128; tt++) {
        int jj = i - 127 + tt;
        acc = fmaf(ps[tt], g_kv[(size_t)jj * KV_W + h * 256 + NOPE + t], acc);
    }
    g_attn[(size_t)i * AOW + h * VD + t] = acc * inv;
}

// ---------------- launch ----------------
extern "C" void kernel_launch(void* const* d_in, const int* in_sizes, int n_in,
                              void* d_out, int out_size)
{
    const float* hidden = (const float*)d_in[0];
    const float* cosp   = (const float*)d_in[1];
    const float* sinp   = (const float*)d_in[2];
    const float* Wq     = (const float*)d_in[3];
    const float* bq     = (const float*)d_in[4];
    const float* Wkva   = (const float*)d_in[5];
    const float* bkva   = (const float*)d_in[6];
    const float* Wkvb   = (const float*)d_in[7];
    const float* Wo     = (const float*)d_in[8];
    const float* bo     = (const float*)d_in[9];
    const float* sinks  = (const float*)d_in[10];
    float* out = (float*)d_out;

    float *q, *ckv, *kv, *attn;
    cudaGetSymbolAddress((void**)&q,    g_q);
    cudaGetSymbolAddress((void**)&ckv,  g_ckv);
    cudaGetSymbolAddress((void**)&kv,   g_kv);
    cudaGetSymbolAddress((void**)&attn, g_attn);

    // 1) q = hidden @ Wq + bq          [2048, 6144] K=2048
    gemm_bf16x3<<<dim3(QW / 128, SEQ / 128), 256>>>(
        hidden, HID, Wq, QW, bq, q, QW, QW, HID);

    // 2) ckv = hidden @ Wkva + bkva    [2048, 576]  K=2048
    gemm_bf16x3<<<dim3((CKV_W + 127) / 128, SEQ / 128), 256>>>(
        hidden, HID, Wkva, CKV_W, bkva, ckv, CKV_W, CKV_W, HID);

    // 3) RoPE on q (in place) and k_rope (-> g_krope)
    rope_q_kernel<<<(SEQ * NH * 32) / 256, 256>>>(cosp, sinp);
    rope_k_kernel<<<(SEQ * 32) / 256, 256>>>(cosp, sinp);

    // 4) kv = ckv[:, :512] @ Wkvb      [2048, 8192] K=512
    gemm_bf16x3<<<dim3(KV_W / 128, SEQ / 128), 256>>>(
        ckv, CKV_W, Wkvb, KV_W, nullptr, kv, KV_W, KV_W, KV_RANK);

    // 5) sliding-window attention with sink
    attn_kernel<<<dim3(SEQ, NH), 128>>>(sinks);

    // 6) out = attn @ Wo + bo          [2048, 2048] K=4096
    gemm_bf16x3<<<dim3(HID / 128, SEQ / 128), 256>>>(
        attn, AOW, Wo, HID, bo, out, HID, HID, AOW);
}

// round 9
// speedup vs baseline: 1.3674x; 1.3142x over previous
#include <cuda_runtime.h>
#include <cuda_bf16.h>
#include <math.h>
#include <stdint.h>

// Problem constants
#define SEQ    2048
#define HID    2048
#define NH     32
#define NOPE   128
#define ROPE_D 64
#define QKD    192
#define VD     128
#define KV_RANK 512
#define SWIN   128
#define CKV_W  576
#define KV_W   8192
#define QW     6144
#define AOW    4096
#define NEGINF (-1000000000.0f)
#define ATTN_SCALE 0.07216878364870323f   // 192^-0.5

// ---------------- scratch (device globals; no allocation allowed) ----------------
__device__ float g_q[(size_t)SEQ * QW];
__device__ float g_ckv[(size_t)SEQ * CKV_W];
__device__ float g_kv[(size_t)SEQ * KV_W];
__device__ float g_krope[(size_t)SEQ * ROPE_D];
__device__ float g_attn[(size_t)SEQ * AOW];

// bf16 hi/lo split buffers
__device__ __nv_bfloat16 g_a2[(size_t)SEQ * 2 * 4096];        // activations, max K=4096
__device__ __nv_bfloat16 g_wq2[(size_t)2 * HID * QW];
__device__ __nv_bfloat16 g_wkva2[(size_t)2 * HID * CKV_W];
__device__ __nv_bfloat16 g_wkvb2[(size_t)2 * KV_RANK * KV_W];
__device__ __nv_bfloat16 g_wo2[(size_t)2 * AOW * HID];

// ---------------- helpers ----------------
__device__ __forceinline__ uint32_t pack2(__nv_bfloat16 a, __nv_bfloat16 b) {
    return (uint32_t)__bfloat16_as_ushort(a) | ((uint32_t)__bfloat16_as_ushort(b) << 16);
}
__device__ __forceinline__ void split1(float x, __nv_bfloat16& hi, __nv_bfloat16& lo) {
    hi = __float2bfloat16(x);
    lo = __float2bfloat16(x - __bfloat162float(hi));
}

// ---- split activations: X[M, ldx] (first K cols) -> Y[M, 2K] = hi | lo ----
__global__ void split_act(const float* __restrict__ X, __nv_bfloat16* __restrict__ Y,
                          int ldx, int K)
{
    int i = blockIdx.x * blockDim.x + threadIdx.x;  // group of 4 elems
    int kq = K >> 2;
    int row = i / kq;
    int c4  = (i - row * kq) * 4;
    float4 v = *reinterpret_cast<const float4*>(&X[(size_t)row * ldx + c4]);
    __nv_bfloat16 h[4], l[4];
    split1(v.x, h[0], l[0]); split1(v.y, h[1], l[1]);
    split1(v.z, h[2], l[2]); split1(v.w, h[3], l[3]);
    uint2 ho, lo2;
    ho.x = pack2(h[0], h[1]); ho.y = pack2(h[2], h[3]);
    lo2.x = pack2(l[0], l[1]); lo2.y = pack2(l[2], l[3]);
    *reinterpret_cast<uint2*>(&Y[(size_t)row * 2 * K + c4])     = ho;
    *reinterpret_cast<uint2*>(&Y[(size_t)row * 2 * K + K + c4]) = lo2;
}

// ---- split weights: X[K, N] -> Y[2K, N] = hi rows | lo rows (flat) ----
__global__ void split_wgt(const float* __restrict__ X, __nv_bfloat16* __restrict__ Y,
                          size_t total /* = K*N */)
{
    size_t i = ((size_t)blockIdx.x * blockDim.x + threadIdx.x) * 4;
    float4 v = *reinterpret_cast<const float4*>(&X[i]);
    __nv_bfloat16 h[4], l[4];
    split1(v.x, h[0], l[0]); split1(v.y, h[1], l[1]);
    split1(v.z, h[2], l[2]); split1(v.w, h[3], l[3]);
    uint2 ho, lo2;
    ho.x = pack2(h[0], h[1]); ho.y = pack2(h[2], h[3]);
    lo2.x = pack2(l[0], l[1]); lo2.y = pack2(l[2], l[3]);
    *reinterpret_cast<uint2*>(&Y[i])         = ho;
    *reinterpret_cast<uint2*>(&Y[total + i]) = lo2;
}

// ---------------- mma / ldmatrix wrappers ----------------
__device__ __forceinline__ void mma16816(float* c, const uint32_t* a, const uint32_t* b)
{
    asm volatile(
        "mma.sync.aligned.m16n8k16.row.col.f32.bf16.bf16.f32 "
        "{%0,%1,%2,%3}, {%4,%5,%6,%7}, {%8,%9}, {%0,%1,%2,%3};\n"
        : "+f"(c[0]), "+f"(c[1]), "+f"(c[2]), "+f"(c[3])
        : "r"(a[0]), "r"(a[1]), "r"(a[2]), "r"(a[3]),
          "r"(b[0]), "r"(b[1]));
}
__device__ __forceinline__ void ldsm4(uint32_t* r, uint32_t addr)
{
    asm volatile("ldmatrix.sync.aligned.m8n8.x4.shared.b16 {%0,%1,%2,%3}, [%4];"
                 : "=r"(r[0]), "=r"(r[1]), "=r"(r[2]), "=r"(r[3]) : "r"(addr));
}
__device__ __forceinline__ void ldsm4t(uint32_t* r, uint32_t addr)
{
    asm volatile("ldmatrix.sync.aligned.m8n8.x4.trans.shared.b16 {%0,%1,%2,%3}, [%4];"
                 : "=r"(r[0]), "=r"(r[1]), "=r"(r[2]), "=r"(r[3]) : "r"(addr));
}
__device__ __forceinline__ void cp16(uint32_t dst, const void* src, int bytes)
{
    asm volatile("cp.async.cg.shared.global [%0], [%1], 16, %2;"
                 :: "r"(dst), "l"(src), "r"(bytes));
}

// ---------------- bf16-split tensor GEMM ----------------
// C[2048, N] = sum over 3 passes of A2[:, segA*K + k] @ B2[segB*K + k, :]  (+bias)
// A2: [M, 2K] (hi|lo cols), B2: [2K, N] (hi|lo rows).
// Block 128x128, BK=32, 256 thr, 8 warps (2m x 4n), cp.async double buffer, ldmatrix.
#define APAD 40
__global__ __launch_bounds__(256) void gemm_split(
    const __nv_bfloat16* __restrict__ A2,
    const __nv_bfloat16* __restrict__ B2,
    const float* __restrict__ bias,
    float* __restrict__ C, int ldc,
    int N, int K)
{
    __shared__ __nv_bfloat16 As[2][128 * APAD];
    __shared__ __nv_bfloat16 Bs[2][32 * 128];

    const int tid  = threadIdx.x;
    const int lane = tid & 31;
    const int w    = tid >> 5;
    const int wm   = w >> 2;
    const int wn   = w & 3;
    const int bm   = blockIdx.y * 128;
    const int bn   = blockIdx.x * 128;
    const int lda2 = 2 * K;

    uint32_t as_base = (uint32_t)__cvta_generic_to_shared(&As[0][0]);
    uint32_t bs_base = (uint32_t)__cvta_generic_to_shared(&Bs[0][0]);

    float acc[4][4][4];
    #pragma unroll
    for (int mi = 0; mi < 4; mi++)
        #pragma unroll
        for (int ni = 0; ni < 4; ni++)
            #pragma unroll
            for (int e = 0; e < 4; e++) acc[mi][ni][e] = 0.0f;

    const int nk = K / 32;
    const int total = 3 * nk;

    // per-thread load coords
    const int am = tid >> 1;                 // A: 2 chunks/row -> rows via tid>>1? no:
    // A tile: 128 rows x 4 chunks(16B) = 512; thread handles lin = tid, tid+256
    // B tile: 32 rows x 16 chunks     = 512

    auto issue = [&](int chunk, int stage) {
        int p = chunk / nk;
        int kk = (chunk - p * nk) * 32;
        int segA = (p == 2) ? 1 : 0;
        int segB = (p == 1) ? 1 : 0;
        const __nv_bfloat16* Abase = A2 + (size_t)segA * K + kk;
        const __nv_bfloat16* Bbase = B2 + (size_t)(segB * K + kk) * N;
        #pragma unroll
        for (int it = 0; it < 2; it++) {
            int lin = tid + it * 256;
            int m = lin >> 2, c = lin & 3;
            const void* src = Abase + (size_t)(bm + m) * lda2 + c * 8;
            cp16(as_base + (stage * 128 * APAD + m * APAD + c * 8) * 2, src, 16);
        }
        #pragma unroll
        for (int it = 0; it < 2; it++) {
            int lin = tid + it * 256;
            int k = lin >> 4, c = lin & 15;
            int col = bn + c * 8;
            const void* src = Bbase + (size_t)k * N + col;
            int phys = c ^ (k & 7);
            cp16(bs_base + (stage * 32 * 128 + k * 128 + phys * 8) * 2, src,
                 (col + 8 <= N) ? 16 : 0);
        }
        asm volatile("cp.async.commit_group;");
    };

    issue(0, 0);

    for (int ch = 0; ch < total; ch++) {
        int st = ch & 1;
        if (ch + 1 < total) {
            issue(ch + 1, (ch + 1) & 1);
            asm volatile("cp.async.wait_group 1;");
        } else {
            asm volatile("cp.async.wait_group 0;");
        }
        __syncthreads();

        #pragma unroll
        for (int ks = 0; ks < 2; ks++) {
            uint32_t af[4][4], bfr[4][2];
            int koff = ks * 16 + (lane >> 4) * 8;
            #pragma unroll
            for (int mt = 0; mt < 4; mt++) {
                int row = wm * 64 + mt * 16 + (lane & 15);
                ldsm4(af[mt], as_base + (st * 128 * APAD + row * APAD + koff) * 2);
            }
            #pragma unroll
            for (int bt = 0; bt < 2; bt++) {
                int krow = ks * 16 + (lane & 15);
                int cL = wn * 4 + bt * 2 + (lane >> 4);
                int phys = cL ^ (krow & 7);
                uint32_t r[4];
                ldsm4t(r, bs_base + (st * 32 * 128 + krow * 128 + phys * 8) * 2);
                bfr[bt * 2][0] = r[0]; bfr[bt * 2][1] = r[1];
                bfr[bt * 2 + 1][0] = r[2]; bfr[bt * 2 + 1][1] = r[3];
            }
            #pragma unroll
            for (int mt = 0; mt < 4; mt++)
                #pragma unroll
                for (int nt = 0; nt < 4; nt++)
                    mma16816(acc[mt][nt], af[mt], bfr[nt]);
        }
        __syncthreads();
    }

    // ---- store ----
    const int g  = lane >> 2;
    const int q4 = (lane & 3) * 2;
    #pragma unroll
    for (int mi = 0; mi < 4; mi++) {
        int r0 = bm + wm * 64 + mi * 16 + g;
        #pragma unroll
        for (int ni = 0; ni < 4; ni++) {
            int c = bn + wn * 32 + ni * 8 + q4;
            if (c < N) {
                float b0 = bias ? bias[c] : 0.0f;
                float b1 = bias ? bias[c + 1] : 0.0f;
                C[(size_t)r0 * ldc + c]           = acc[mi][ni][0] + b0;
                C[(size_t)r0 * ldc + c + 1]       = acc[mi][ni][1] + b1;
                C[(size_t)(r0 + 8) * ldc + c]     = acc[mi][ni][2] + b0;
                C[(size_t)(r0 + 8) * ldc + c + 1] = acc[mi][ni][3] + b1;
            }
        }
    }
}

// ---------------- RoPE on q (in place, last 64 dims of each head) ----------------
__global__ void rope_q_kernel(const float* __restrict__ cosp,
                              const float* __restrict__ sinp)
{
    int idx = blockIdx.x * blockDim.x + threadIdx.x;
    int r = idx & 31;
    int h = (idx >> 5) & 31;
    int i = idx >> 10;
    float* base = &g_q[(size_t)i * QW + h * QKD + NOPE];
    float x0 = base[r];
    float x1 = base[r + 32];
    float c0 = cosp[i * ROPE_D + r];
    float c1 = cosp[i * ROPE_D + 32 + r];
    float s0 = sinp[i * ROPE_D + r];
    float s1 = sinp[i * ROPE_D + 32 + r];
    base[r]      = x0 * c0 - x1 * s0;
    base[r + 32] = x1 * c1 + x0 * s1;
}

__global__ void rope_k_kernel(const float* __restrict__ cosp,
                              const float* __restrict__ sinp)
{
    int idx = blockIdx.x * blockDim.x + threadIdx.x;
    int r = idx & 31;
    int i = idx >> 5;
    const float* base = &g_ckv[(size_t)i * CKV_W + KV_RANK];
    float x0 = base[r];
    float x1 = base[r + 32];
    float c0 = cosp[i * ROPE_D + r];
    float c1 = cosp[i * ROPE_D + 32 + r];
    float s0 = sinp[i * ROPE_D + r];
    float s1 = sinp[i * ROPE_D + 32 + r];
    g_krope[(size_t)i * ROPE_D + r]      = x0 * c0 - x1 * s0;
    g_krope[(size_t)i * ROPE_D + 32 + r] = x1 * c1 + x0 * s1;
}

// ---------------- sliding-window attention with sink ----------------
__global__ __launch_bounds__(128) void attn_kernel(const float* __restrict__ sinks)
{
    const int i = blockIdx.x;
    const int h = blockIdx.y;
    const int t = threadIdx.x;

    __shared__ float qs[QKD];
    __shared__ float red[128];
    __shared__ float ps[128];

    const float* qp = &g_q[(size_t)i * QW + h * QKD];
    if (t < 128)       qs[t]       = qp[t];
    if (t + 128 < QKD) qs[t + 128] = qp[t + 128];
    __syncthreads();

    const int j = i - 127 + t;
    float l = NEGINF;
    if (j >= 0) {
        const float* kp = &g_kv[(size_t)j * KV_W + h * 256];
        const float* rp = &g_krope[(size_t)j * ROPE_D];
        float acc = 0.0f;
        #pragma unroll 8
        for (int d = 0; d < NOPE; d++) acc = fmaf(qs[d], kp[d], acc);
        #pragma unroll 8
        for (int d = 0; d < ROPE_D; d++) acc = fmaf(qs[NOPE + d], rp[d], acc);
        l = acc * ATTN_SCALE;
    }

    red[t] = l;
    __syncthreads();
    #pragma unroll
    for (int s = 64; s > 0; s >>= 1) {
        if (t < s) red[t] = fmaxf(red[t], red[t + s]);
        __syncthreads();
    }
    const float snk = sinks[h];
    const float m = fmaxf(red[0], snk);
    __syncthreads();

    float p = (j >= 0) ? __expf(l - m) : 0.0f;
    ps[t] = p;
    red[t] = p;
    __syncthreads();
    #pragma unroll
    for (int s = 64; s > 0; s >>= 1) {
        if (t < s) red[t] += red[t + s];
        __syncthreads();
    }
    const float inv = 1.0f / (red[0] + __expf(snk - m));

    const int t0 = (i < 127) ? (127 - i) : 0;
    float acc = 0.0f;
    for (int tt = t0; tt < 128; tt++) {
        int jj = i - 127 + tt;
        acc = fmaf(ps[tt], g_kv[(size_t)jj * KV_W + h * 256 + NOPE + t], acc);
    }
    g_attn[(size_t)i * AOW + h * VD + t] = acc * inv;
}

// ---------------- launch ----------------
extern "C" void kernel_launch(void* const* d_in, const int* in_sizes, int n_in,
                              void* d_out, int out_size)
{
    const float* hidden = (const float*)d_in[0];
    const float* cosp   = (const float*)d_in[1];
    const float* sinp   = (const float*)d_in[2];
    const float* Wq     = (const float*)d_in[3];
    const float* bq     = (const float*)d_in[4];
    const float* Wkva   = (const float*)d_in[5];
    const float* bkva   = (const float*)d_in[6];
    const float* Wkvb   = (const float*)d_in[7];
    const float* Wo     = (const float*)d_in[8];
    const float* bo     = (const float*)d_in[9];
    const float* sinks  = (const float*)d_in[10];
    float* out = (float*)d_out;

    float *q, *ckv, *kv, *attn;
    __nv_bfloat16 *a2, *wq2, *wkva2, *wkvb2, *wo2;
    cudaGetSymbolAddress((void**)&q,     g_q);
    cudaGetSymbolAddress((void**)&ckv,   g_ckv);
    cudaGetSymbolAddress((void**)&kv,    g_kv);
    cudaGetSymbolAddress((void**)&attn,  g_attn);
    cudaGetSymbolAddress((void**)&a2,    g_a2);
    cudaGetSymbolAddress((void**)&wq2,   g_wq2);
    cudaGetSymbolAddress((void**)&wkva2, g_wkva2);
    cudaGetSymbolAddress((void**)&wkvb2, g_wkvb2);
    cudaGetSymbolAddress((void**)&wo2,   g_wo2);

    // ---- weight splits ----
    split_wgt<<<(size_t)HID * QW / 4 / 256, 256>>>(Wq, wq2, (size_t)HID * QW);
    split_wgt<<<(size_t)HID * CKV_W / 4 / 256, 256>>>(Wkva, wkva2, (size_t)HID * CKV_W);
    split_wgt<<<(size_t)KV_RANK * KV_W / 4 / 256, 256>>>(Wkvb, wkvb2, (size_t)KV_RANK * KV_W);
    split_wgt<<<(size_t)AOW * HID / 4 / 256, 256>>>(Wo, wo2, (size_t)AOW * HID);

    // ---- hidden split, then Q and KVA projections ----
    split_act<<<SEQ * HID / 4 / 256, 256>>>(hidden, a2, HID, HID);
    gemm_split<<<dim3(QW / 128, SEQ / 128), 256>>>(a2, wq2, bq, q, QW, QW, HID);
    gemm_split<<<dim3((CKV_W + 127) / 128, SEQ / 128), 256>>>(a2, wkva2, bkva, ckv, CKV_W, CKV_W, HID);

    // ---- RoPE ----
    rope_q_kernel<<<(SEQ * NH * 32) / 256, 256>>>(cosp, sinp);
    rope_k_kernel<<<(SEQ * 32) / 256, 256>>>(cosp, sinp);

    // ---- latent split, KV expansion ----
    split_act<<<SEQ * KV_RANK / 4 / 256, 256>>>(ckv, a2, CKV_W, KV_RANK);
    gemm_split<<<dim3(KV_W / 128, SEQ / 128), 256>>>(a2, wkvb2, nullptr, kv, KV_W, KV_W, KV_RANK);

    // ---- attention ----
    attn_kernel<<<dim3(SEQ, NH), 128>>>(sinks);

    // ---- attn split, output projection ----
    split_act<<<SEQ * AOW / 4 / 256, 256>>>(attn, a2, AOW, AOW);
    gemm_split<<<dim3(HID / 128, SEQ / 128), 256>>>(a2, wo2, bo, out, HID, HID, AOW);
}

// round 10
// speedup vs baseline: 5.1464x; 3.7637x over previous
#include <cuda_runtime.h>
#include <cuda_bf16.h>
#include <math.h>
#include <stdint.h>

// Problem constants
#define SEQ    2048
#define HID    2048
#define NH     32
#define NOPE   128
#define ROPE_D 64
#define QKD    192
#define VD     128
#define KV_RANK 512
#define SWIN   128
#define CKV_W  576
#define KV_W   8192
#define QW     6144
#define AOW    4096
#define NEGINF (-1000000000.0f)
#define ATTN_SCALE 0.07216878364870323f   // 192^-0.5

// ---------------- scratch (device globals; no allocation allowed) ----------------
__device__ float g_q[(size_t)SEQ * QW];
__device__ float g_ckv[(size_t)SEQ * CKV_W];
__device__ float g_kv[(size_t)SEQ * KV_W];
__device__ float g_krope[(size_t)SEQ * ROPE_D];
__device__ float g_attn[(size_t)SEQ * AOW];

// bf16 hi/lo split buffers
__device__ __nv_bfloat16 g_a2[(size_t)SEQ * 2 * 4096];
__device__ __nv_bfloat16 g_wq2[(size_t)2 * HID * QW];
__device__ __nv_bfloat16 g_wkva2[(size_t)2 * HID * CKV_W];
__device__ __nv_bfloat16 g_wkvb2[(size_t)2 * KV_RANK * KV_W];
__device__ __nv_bfloat16 g_wo2[(size_t)2 * AOW * HID];

// ---------------- helpers ----------------
__device__ __forceinline__ uint32_t pack2(__nv_bfloat16 a, __nv_bfloat16 b) {
    return (uint32_t)__bfloat16_as_ushort(a) | ((uint32_t)__bfloat16_as_ushort(b) << 16);
}
__device__ __forceinline__ void split1(float x, __nv_bfloat16& hi, __nv_bfloat16& lo) {
    hi = __float2bfloat16(x);
    lo = __float2bfloat16(x - __bfloat162float(hi));
}

__global__ void split_act(const float* __restrict__ X, __nv_bfloat16* __restrict__ Y,
                          int ldx, int K)
{
    int i = blockIdx.x * blockDim.x + threadIdx.x;
    int kq = K >> 2;
    int row = i / kq;
    int c4  = (i - row * kq) * 4;
    float4 v = *reinterpret_cast<const float4*>(&X[(size_t)row * ldx + c4]);
    __nv_bfloat16 h[4], l[4];
    split1(v.x, h[0], l[0]); split1(v.y, h[1], l[1]);
    split1(v.z, h[2], l[2]); split1(v.w, h[3], l[3]);
    uint2 ho, lo2;
    ho.x = pack2(h[0], h[1]); ho.y = pack2(h[2], h[3]);
    lo2.x = pack2(l[0], l[1]); lo2.y = pack2(l[2], l[3]);
    *reinterpret_cast<uint2*>(&Y[(size_t)row * 2 * K + c4])     = ho;
    *reinterpret_cast<uint2*>(&Y[(size_t)row * 2 * K + K + c4]) = lo2;
}

__global__ void split_wgt(const float* __restrict__ X, __nv_bfloat16* __restrict__ Y,
                          size_t total)
{
    size_t i = ((size_t)blockIdx.x * blockDim.x + threadIdx.x) * 4;
    float4 v = *reinterpret_cast<const float4*>(&X[i]);
    __nv_bfloat16 h[4], l[4];
    split1(v.x, h[0], l[0]); split1(v.y, h[1], l[1]);
    split1(v.z, h[2], l[2]); split1(v.w, h[3], l[3]);
    uint2 ho, lo2;
    ho.x = pack2(h[0], h[1]); ho.y = pack2(h[2], h[3]);
    lo2.x = pack2(l[0], l[1]); lo2.y = pack2(l[2], l[3]);
    *reinterpret_cast<uint2*>(&Y[i])         = ho;
    *reinterpret_cast<uint2*>(&Y[total + i]) = lo2;
}

// ---------------- mma / ldmatrix wrappers ----------------
__device__ __forceinline__ void mma16816(float* c, const uint32_t* a, const uint32_t* b)
{
    asm volatile(
        "mma.sync.aligned.m16n8k16.row.col.f32.bf16.bf16.f32 "
        "{%0,%1,%2,%3}, {%4,%5,%6,%7}, {%8,%9}, {%0,%1,%2,%3};\n"
        : "+f"(c[0]), "+f"(c[1]), "+f"(c[2]), "+f"(c[3])
        : "r"(a[0]), "r"(a[1]), "r"(a[2]), "r"(a[3]),
          "r"(b[0]), "r"(b[1]));
}
__device__ __forceinline__ void ldsm4(uint32_t* r, uint32_t addr)
{
    asm volatile("ldmatrix.sync.aligned.m8n8.x4.shared.b16 {%0,%1,%2,%3}, [%4];"
                 : "=r"(r[0]), "=r"(r[1]), "=r"(r[2]), "=r"(r[3]) : "r"(addr));
}
__device__ __forceinline__ void ldsm4t(uint32_t* r, uint32_t addr)
{
    asm volatile("ldmatrix.sync.aligned.m8n8.x4.trans.shared.b16 {%0,%1,%2,%3}, [%4];"
                 : "=r"(r[0]), "=r"(r[1]), "=r"(r[2]), "=r"(r[3]) : "r"(addr));
}
__device__ __forceinline__ void cp16(uint32_t dst, const void* src, int bytes)
{
    asm volatile("cp.async.cg.shared.global [%0], [%1], 16, %2;"
                 :: "r"(dst), "l"(src), "r"(bytes));
}

// ---------------- bf16-split tensor GEMM, 4-stage cp.async pipeline ----------------
#define APAD 40
#define NSTAGES 4
#define AS_STAGE (128 * APAD)          // halves per A stage
#define BS_STAGE (32 * 128)            // halves per B stage
#define GEMM_SMEM (NSTAGES * (AS_STAGE + BS_STAGE) * 2)

__global__ __launch_bounds__(256) void gemm_split(
    const __nv_bfloat16* __restrict__ A2,
    const __nv_bfloat16* __restrict__ B2,
    const float* __restrict__ bias,
    float* __restrict__ C, int ldc,
    int N, int K)
{
    extern __shared__ __nv_bfloat16 dynsmem[];

    const int tid  = threadIdx.x;
    const int lane = tid & 31;
    const int w    = tid >> 5;
    const int wm   = w >> 2;
    const int wn   = w & 3;
    const int bm   = blockIdx.y * 128;
    const int bn   = blockIdx.x * 128;
    const int lda2 = 2 * K;

    uint32_t as_base = (uint32_t)__cvta_generic_to_shared(dynsmem);
    uint32_t bs_base = as_base + NSTAGES * AS_STAGE * 2;

    float acc[4][4][4];
    #pragma unroll
    for (int mi = 0; mi < 4; mi++)
        #pragma unroll
        for (int ni = 0; ni < 4; ni++)
            #pragma unroll
            for (int e = 0; e < 4; e++) acc[mi][ni][e] = 0.0f;

    const int nk = K / 32;
    const int total = 3 * nk;

    auto issue = [&](int chunk, int stage) {
        if (chunk < total) {
            int p = chunk / nk;
            int kk = (chunk - p * nk) * 32;
            int segA = (p == 2) ? 1 : 0;
            int segB = (p == 1) ? 1 : 0;
            const __nv_bfloat16* Abase = A2 + (size_t)segA * K + kk;
            const __nv_bfloat16* Bbase = B2 + (size_t)(segB * K + kk) * N;
            #pragma unroll
            for (int it = 0; it < 2; it++) {
                int lin = tid + it * 256;
                int m = lin >> 2, c = lin & 3;
                const void* src = Abase + (size_t)(bm + m) * lda2 + c * 8;
                cp16(as_base + (stage * AS_STAGE + m * APAD + c * 8) * 2, src, 16);
            }
            #pragma unroll
            for (int it = 0; it < 2; it++) {
                int lin = tid + it * 256;
                int k = lin >> 4, c = lin & 15;
                int col = bn + c * 8;
                const void* src = Bbase + (size_t)k * N + col;
                int phys = c ^ (k & 7);
                cp16(bs_base + (stage * BS_STAGE + k * 128 + phys * 8) * 2, src,
                     (col + 8 <= N) ? 16 : 0);
            }
        }
        asm volatile("cp.async.commit_group;");   // always commit (empty tail groups)
    };

    issue(0, 0);
    issue(1, 1);
    issue(2, 2);

    for (int ch = 0; ch < total; ch++) {
        int st = ch & (NSTAGES - 1);
        asm volatile("cp.async.wait_group %0;" :: "n"(NSTAGES - 2));
        __syncthreads();

        issue(ch + NSTAGES - 1, (ch + NSTAGES - 1) & (NSTAGES - 1));

        #pragma unroll
        for (int ks = 0; ks < 2; ks++) {
            uint32_t af[4][4], bfr[4][2];
            int koff = ks * 16 + (lane >> 4) * 8;
            #pragma unroll
            for (int mt = 0; mt < 4; mt++) {
                int row = wm * 64 + mt * 16 + (lane & 15);
                ldsm4(af[mt], as_base + (st * AS_STAGE + row * APAD + koff) * 2);
            }
            #pragma unroll
            for (int bt = 0; bt < 2; bt++) {
                int krow = ks * 16 + (lane & 15);
                int cL = wn * 4 + bt * 2 + (lane >> 4);
                int phys = cL ^ (krow & 7);
                uint32_t r[4];
                ldsm4t(r, bs_base + (st * BS_STAGE + krow * 128 + phys * 8) * 2);
                bfr[bt * 2][0] = r[0]; bfr[bt * 2][1] = r[1];
                bfr[bt * 2 + 1][0] = r[2]; bfr[bt * 2 + 1][1] = r[3];
            }
            #pragma unroll
            for (int mt = 0; mt < 4; mt++)
                #pragma unroll
                for (int nt = 0; nt < 4; nt++)
                    mma16816(acc[mt][nt], af[mt], bfr[nt]);
        }
        __syncthreads();
    }

    // ---- store ----
    const int g  = lane >> 2;
    const int q4 = (lane & 3) * 2;
    #pragma unroll
    for (int mi = 0; mi < 4; mi++) {
        int r0 = bm + wm * 64 + mi * 16 + g;
        #pragma unroll
        for (int ni = 0; ni < 4; ni++) {
            int c = bn + wn * 32 + ni * 8 + q4;
            if (c < N) {
                float b0 = bias ? bias[c] : 0.0f;
                float b1 = bias ? bias[c + 1] : 0.0f;
                C[(size_t)r0 * ldc + c]           = acc[mi][ni][0] + b0;
                C[(size_t)r0 * ldc + c + 1]       = acc[mi][ni][1] + b1;
                C[(size_t)(r0 + 8) * ldc + c]     = acc[mi][ni][2] + b0;
                C[(size_t)(r0 + 8) * ldc + c + 1] = acc[mi][ni][3] + b1;
            }
        }
    }
}

// ---------------- RoPE kernels ----------------
__global__ void rope_q_kernel(const float* __restrict__ cosp,
                              const float* __restrict__ sinp)
{
    int idx = blockIdx.x * blockDim.x + threadIdx.x;
    int r = idx & 31;
    int h = (idx >> 5) & 31;
    int i = idx >> 10;
    float* base = &g_q[(size_t)i * QW + h * QKD + NOPE];
    float x0 = base[r];
    float x1 = base[r + 32];
    float c0 = cosp[i * ROPE_D + r];
    float c1 = cosp[i * ROPE_D + 32 + r];
    float s0 = sinp[i * ROPE_D + r];
    float s1 = sinp[i * ROPE_D + 32 + r];
    base[r]      = x0 * c0 - x1 * s0;
    base[r + 32] = x1 * c1 + x0 * s1;
}

__global__ void rope_k_kernel(const float* __restrict__ cosp,
                              const float* __restrict__ sinp)
{
    int idx = blockIdx.x * blockDim.x + threadIdx.x;
    int r = idx & 31;
    int i = idx >> 5;
    const float* base = &g_ckv[(size_t)i * CKV_W + KV_RANK];
    float x0 = base[r];
    float x1 = base[r + 32];
    float c0 = cosp[i * ROPE_D + r];
    float c1 = cosp[i * ROPE_D + 32 + r];
    float s0 = sinp[i * ROPE_D + r];
    float s1 = sinp[i * ROPE_D + 32 + r];
    g_krope[(size_t)i * ROPE_D + r]      = x0 * c0 - x1 * s0;
    g_krope[(size_t)i * ROPE_D + 32 + r] = x1 * c1 + x0 * s1;
}

// ---------------- query-tiled sliding-window attention with sink ----------------
// Block = (16-query tile, head). 256 threads. K/V staged through smem in 16-key chunks.
#define QT   16
#define QPAD 196
#define KPAD 196
#define VPAD 132
#define LW   144
__global__ __launch_bounds__(256) void attn_tile_kernel(const float* __restrict__ sinks)
{
    __shared__ float Qs[QT][QPAD];
    __shared__ float Ks[16][KPAD];
    __shared__ float Ls[QT][LW];
    __shared__ float Vs[16][VPAD];

    const int i0    = blockIdx.x * QT;
    const int h     = blockIdx.y;
    const int tid   = threadIdx.x;
    const int jbase = i0 - 127;

    // ---- load Q tile: 16 rows x 192 floats ----
    #pragma unroll
    for (int it = 0; it < 3; it++) {
        int lin = tid + it * 256;          // 0..767
        int r   = lin / 48;
        int c4  = (lin % 48) * 4;
        float4 v = *reinterpret_cast<const float4*>(
            &g_q[(size_t)(i0 + r) * QW + h * QKD + c4]);
        *reinterpret_cast<float4*>(&Qs[r][c4]) = v;
    }
    __syncthreads();

    const int q = tid >> 4;   // 0..15  query within tile
    const int j = tid & 15;   // 0..15  key slot within chunk

    // ---- logits: 9 chunks of 16 key slots (slots 0..143 cover keys [i0-127, i0+16]) ----
    for (int c = 0; c < 9; c++) {
        #pragma unroll
        for (int it = 0; it < 3; it++) {
            int lin = tid + it * 256;
            int r   = lin / 48;
            int c4  = (lin % 48) * 4;
            int key = jbase + c * 16 + r;
            float4 v = make_float4(0.f, 0.f, 0.f, 0.f);
            if (key >= 0 && key < SEQ) {
                if (c4 < NOPE)
                    v = *reinterpret_cast<const float4*>(
                        &g_kv[(size_t)key * KV_W + h * 256 + c4]);
                else
                    v = *reinterpret_cast<const float4*>(
                        &g_krope[(size_t)key * ROPE_D + (c4 - NOPE)]);
            }
            *reinterpret_cast<float4*>(&Ks[r][c4]) = v;
        }
        __syncthreads();
        float acc = 0.0f;
        #pragma unroll 8
        for (int d = 0; d < QKD; d++) acc = fmaf(Qs[q][d], Ks[j][d], acc);
        Ls[q][c * 16 + j] = acc;
        __syncthreads();
    }

    // ---- softmax per row (warp w handles rows w and w+8) ----
    {
        const int lane = tid & 31;
        const int wrp  = tid >> 5;
        const float snk = sinks[h];
        #pragma unroll
        for (int rr = 0; rr < 2; rr++) {
            int row = wrp + rr * 8;
            float vals[5];
            float m = NEGINF;
            #pragma unroll
            for (int u = 0; u < 5; u++) {
                int t = lane + u * 32;
                float x = NEGINF;
                if (t < 143 && t >= row && t <= row + 127 && (jbase + t) >= 0)
                    x = Ls[row][t] * ATTN_SCALE;
                vals[u] = x;
                m = fmaxf(m, x);
            }
            #pragma unroll
            for (int o = 16; o > 0; o >>= 1) m = fmaxf(m, __shfl_xor_sync(0xFFFFFFFFu, m, o));
            m = fmaxf(m, snk);
            float s = 0.0f;
            #pragma unroll
            for (int u = 0; u < 5; u++) {
                float p = (vals[u] > 0.5f * NEGINF) ? __expf(vals[u] - m) : 0.0f;
                vals[u] = p;
                s += p;
            }
            #pragma unroll
            for (int o = 16; o > 0; o >>= 1) s += __shfl_xor_sync(0xFFFFFFFFu, s, o);
            float inv = 1.0f / (s + __expf(snk - m));
            #pragma unroll
            for (int u = 0; u < 5; u++) {
                int t = lane + u * 32;
                if (t < LW) Ls[row][t] = vals[u] * inv;
            }
        }
    }
    __syncthreads();

    // ---- output: O[16][128] = P[16][144] @ V[144][128], V staged in chunks ----
    const int dg = tid & 15;
    float oacc[8];
    #pragma unroll
    for (int e = 0; e < 8; e++) oacc[e] = 0.0f;

    for (int c = 0; c < 9; c++) {
        #pragma unroll
        for (int it = 0; it < 2; it++) {
            int lin = tid + it * 256;
            int r   = lin >> 5;
            int c4  = (lin & 31) * 4;
            int key = jbase + c * 16 + r;
            float4 v = make_float4(0.f, 0.f, 0.f, 0.f);
            if (key >= 0 && key < SEQ)
                v = *reinterpret_cast<const float4*>(
                    &g_kv[(size_t)key * KV_W + h * 256 + NOPE + c4]);
            *reinterpret_cast<float4*>(&Vs[r][c4]) = v;
        }
        __syncthreads();
        #pragma unroll
        for (int r = 0; r < 16; r++) {
            float p = Ls[q][c * 16 + r];
            float4 v0 = *reinterpret_cast<float4*>(&Vs[r][dg * 8]);
            float4 v1 = *reinterpret_cast<float4*>(&Vs[r][dg * 8 + 4]);
            oacc[0] = fmaf(p, v0.x, oacc[0]);
            oacc[1] = fmaf(p, v0.y, oacc[1]);
            oacc[2] = fmaf(p, v0.z, oacc[2]);
            oacc[3] = fmaf(p, v0.w, oacc[3]);
            oacc[4] = fmaf(p, v1.x, oacc[4]);
            oacc[5] = fmaf(p, v1.y, oacc[5]);
            oacc[6] = fmaf(p, v1.z, oacc[6]);
            oacc[7] = fmaf(p, v1.w, oacc[7]);
        }
        __syncthreads();
    }

    size_t obase = (size_t)(i0 + q) * AOW + h * VD + dg * 8;
    float4 o0 = make_float4(oacc[0], oacc[1], oacc[2], oacc[3]);
    float4 o1 = make_float4(oacc[4], oacc[5], oacc[6], oacc[7]);
    *reinterpret_cast<float4*>(&g_attn[obase])     = o0;
    *reinterpret_cast<float4*>(&g_attn[obase + 4]) = o1;
}

// ---------------- launch ----------------
extern "C" void kernel_launch(void* const* d_in, const int* in_sizes, int n_in,
                              void* d_out, int out_size)
{
    const float* hidden = (const float*)d_in[0];
    const float* cosp   = (const float*)d_in[1];
    const float* sinp   = (const float*)d_in[2];
    const float* Wq     = (const float*)d_in[3];
    const float* bq     = (const float*)d_in[4];
    const float* Wkva   = (const float*)d_in[5];
    const float* bkva   = (const float*)d_in[6];
    const float* Wkvb   = (const float*)d_in[7];
    const float* Wo     = (const float*)d_in[8];
    const float* bo     = (const float*)d_in[9];
    const float* sinks  = (const float*)d_in[10];
    float* out = (float*)d_out;

    float *q, *ckv, *kv, *attn;
    __nv_bfloat16 *a2, *wq2, *wkva2, *wkvb2, *wo2;
    cudaGetSymbolAddress((void**)&q,     g_q);
    cudaGetSymbolAddress((void**)&ckv,   g_ckv);
    cudaGetSymbolAddress((void**)&kv,    g_kv);
    cudaGetSymbolAddress((void**)&attn,  g_attn);
    cudaGetSymbolAddress((void**)&a2,    g_a2);
    cudaGetSymbolAddress((void**)&wq2,   g_wq2);
    cudaGetSymbolAddress((void**)&wkva2, g_wkva2);
    cudaGetSymbolAddress((void**)&wkvb2, g_wkvb2);
    cudaGetSymbolAddress((void**)&wo2,   g_wo2);

    cudaFuncSetAttribute(gemm_split,
                         cudaFuncAttributeMaxDynamicSharedMemorySize, GEMM_SMEM);

    // ---- weight splits ----
    split_wgt<<<(size_t)HID * QW / 4 / 256, 256>>>(Wq, wq2, (size_t)HID * QW);
    split_wgt<<<(size_t)HID * CKV_W / 4 / 256, 256>>>(Wkva, wkva2, (size_t)HID * CKV_W);
    split_wgt<<<(size_t)KV_RANK * KV_W / 4 / 256, 256>>>(Wkvb, wkvb2, (size_t)KV_RANK * KV_W);
    split_wgt<<<(size_t)AOW * HID / 4 / 256, 256>>>(Wo, wo2, (size_t)AOW * HID);

    // ---- hidden split, Q and KVA projections ----
    split_act<<<SEQ * HID / 4 / 256, 256>>>(hidden, a2, HID, HID);
    gemm_split<<<dim3(QW / 128, SEQ / 128), 256, GEMM_SMEM>>>(
        a2, wq2, bq, q, QW, QW, HID);
    gemm_split<<<dim3((CKV_W + 127) / 128, SEQ / 128), 256, GEMM_SMEM>>>(
        a2, wkva2, bkva, ckv, CKV_W, CKV_W, HID);

    // ---- RoPE ----
    rope_q_kernel<<<(SEQ * NH * 32) / 256, 256>>>(cosp, sinp);
    rope_k_kernel<<<(SEQ * 32) / 256, 256>>>(cosp, sinp);

    // ---- latent split, KV expansion ----
    split_act<<<SEQ * KV_RANK / 4 / 256, 256>>>(ckv, a2, CKV_W, KV_RANK);
    gemm_split<<<dim3(KV_W / 128, SEQ / 128), 256, GEMM_SMEM>>>(
        a2, wkvb2, nullptr, kv, KV_W, KV_W, KV_RANK);

    // ---- attention (query-tiled) ----
    attn_tile_kernel<<<dim3(SEQ / QT, NH), 256>>>(sinks);

    // ---- attn split, output projection ----
    split_act<<<SEQ * AOW / 4 / 256, 256>>>(attn, a2, AOW, AOW);
    gemm_split<<<dim3(HID / 128, SEQ / 128), 256, GEMM_SMEM>>>(
        a2, wo2, bo, out, HID, HID, AOW);
}

// round 11
// speedup vs baseline: 5.7210x; 1.1116x over previous
#include <cuda_runtime.h>
#include <cuda_bf16.h>
#include <math.h>
#include <stdint.h>

// Problem constants
#define SEQ    2048
#define HID    2048
#define NH     32
#define NOPE   128
#define ROPE_D 64
#define QKD    192
#define VD     128
#define KV_RANK 512
#define SWIN   128
#define CKV_W  576
#define KV_W   8192
#define QW     6144
#define AOW    4096
#define NEGINF (-1000000000.0f)
#define ATTN_SCALE 0.07216878364870323f   // 192^-0.5

// ---------------- scratch (device globals; no allocation allowed) ----------------
__device__ float g_q[(size_t)SEQ * QW];
__device__ float g_ckv[(size_t)SEQ * CKV_W];
__device__ float g_kv[(size_t)SEQ * KV_W];
__device__ float g_krope[(size_t)SEQ * ROPE_D];
__device__ float g_attn[(size_t)SEQ * AOW];

// bf16 hi/lo split buffers
__device__ __nv_bfloat16 g_a2[(size_t)SEQ * 2 * 4096];
__device__ __nv_bfloat16 g_wq2[(size_t)2 * HID * QW];
__device__ __nv_bfloat16 g_wkva2[(size_t)2 * HID * CKV_W];
__device__ __nv_bfloat16 g_wkvb2[(size_t)2 * KV_RANK * KV_W];
__device__ __nv_bfloat16 g_wo2[(size_t)2 * AOW * HID];

// ---------------- helpers ----------------
__device__ __forceinline__ uint32_t pack2(__nv_bfloat16 a, __nv_bfloat16 b) {
    return (uint32_t)__bfloat16_as_ushort(a) | ((uint32_t)__bfloat16_as_ushort(b) << 16);
}
__device__ __forceinline__ void split1(float x, __nv_bfloat16& hi, __nv_bfloat16& lo) {
    hi = __float2bfloat16(x);
    lo = __float2bfloat16(x - __bfloat162float(hi));
}

__global__ void split_act(const float* __restrict__ X, __nv_bfloat16* __restrict__ Y,
                          int ldx, int K)
{
    int i = blockIdx.x * blockDim.x + threadIdx.x;
    int kq = K >> 2;
    int row = i / kq;
    int c4  = (i - row * kq) * 4;
    float4 v = *reinterpret_cast<const float4*>(&X[(size_t)row * ldx + c4]);
    __nv_bfloat16 h[4], l[4];
    split1(v.x, h[0], l[0]); split1(v.y, h[1], l[1]);
    split1(v.z, h[2], l[2]); split1(v.w, h[3], l[3]);
    uint2 ho, lo2;
    ho.x = pack2(h[0], h[1]); ho.y = pack2(h[2], h[3]);
    lo2.x = pack2(l[0], l[1]); lo2.y = pack2(l[2], l[3]);
    *reinterpret_cast<uint2*>(&Y[(size_t)row * 2 * K + c4])     = ho;
    *reinterpret_cast<uint2*>(&Y[(size_t)row * 2 * K + K + c4]) = lo2;
}

__global__ void split_wgt(const float* __restrict__ X, __nv_bfloat16* __restrict__ Y,
                          size_t total)
{
    size_t i = ((size_t)blockIdx.x * blockDim.x + threadIdx.x) * 4;
    float4 v = *reinterpret_cast<const float4*>(&X[i]);
    __nv_bfloat16 h[4], l[4];
    split1(v.x, h[0], l[0]); split1(v.y, h[1], l[1]);
    split1(v.z, h[2], l[2]); split1(v.w, h[3], l[3]);
    uint2 ho, lo2;
    ho.x = pack2(h[0], h[1]); ho.y = pack2(h[2], h[3]);
    lo2.x = pack2(l[0], l[1]); lo2.y = pack2(l[2], l[3]);
    *reinterpret_cast<uint2*>(&Y[i])         = ho;
    *reinterpret_cast<uint2*>(&Y[total + i]) = lo2;
}

// ---------------- mma / ldmatrix wrappers ----------------
__device__ __forceinline__ void mma16816(float* c, const uint32_t* a, const uint32_t* b)
{
    asm volatile(
        "mma.sync.aligned.m16n8k16.row.col.f32.bf16.bf16.f32 "
        "{%0,%1,%2,%3}, {%4,%5,%6,%7}, {%8,%9}, {%0,%1,%2,%3};\n"
        : "+f"(c[0]), "+f"(c[1]), "+f"(c[2]), "+f"(c[3])
        : "r"(a[0]), "r"(a[1]), "r"(a[2]), "r"(a[3]),
          "r"(b[0]), "r"(b[1]));
}
__device__ __forceinline__ void ldsm4(uint32_t* r, uint32_t addr)
{
    asm volatile("ldmatrix.sync.aligned.m8n8.x4.shared.b16 {%0,%1,%2,%3}, [%4];"
                 : "=r"(r[0]), "=r"(r[1]), "=r"(r[2]), "=r"(r[3]) : "r"(addr));
}
__device__ __forceinline__ void ldsm4t(uint32_t* r, uint32_t addr)
{
    asm volatile("ldmatrix.sync.aligned.m8n8.x4.trans.shared.b16 {%0,%1,%2,%3}, [%4];"
                 : "=r"(r[0]), "=r"(r[1]), "=r"(r[2]), "=r"(r[3]) : "r"(addr));
}
__device__ __forceinline__ void cp16(uint32_t dst, const void* src, int bytes)
{
    asm volatile("cp.async.cg.shared.global [%0], [%1], 16, %2;"
                 :: "r"(dst), "l"(src), "r"(bytes));
}

// ---------------- fused bf16x3 tensor GEMM ----------------
// C[2048, N] = Ah@Bh + Ah@Bl + Al@Bh   (+bias), all staged per 32-k chunk.
// A2: [M, 2K] (hi|lo cols), B2: [2K, N] (hi|lo rows).
// Block 128x128, BK=32, 256 thr, 8 warps (2m x 4n), 3-stage cp.async, 1 barrier/chunk.
#define APAD 40
#define AH_OFF 0
#define AL_OFF (128 * APAD)                 // 5120 halves
#define BH_OFF (2 * 128 * APAD)             // 10240
#define BL_OFF (2 * 128 * APAD + 32 * 128)  // 14336
#define STG    (2 * 128 * APAD + 2 * 32 * 128)   // 18432 halves per stage
#define NSTAGES 3
#define GEMM_SMEM (NSTAGES * STG * 2)       // 110592 bytes

__global__ __launch_bounds__(256) void gemm_split(
    const __nv_bfloat16* __restrict__ A2,
    const __nv_bfloat16* __restrict__ B2,
    const float* __restrict__ bias,
    float* __restrict__ C, int ldc,
    int N, int K)
{
    extern __shared__ __nv_bfloat16 dynsmem[];

    const int tid  = threadIdx.x;
    const int lane = tid & 31;
    const int w    = tid >> 5;
    const int wm   = w >> 2;
    const int wn   = w & 3;
    const int bm   = blockIdx.y * 128;
    const int bn   = blockIdx.x * 128;
    const int lda2 = 2 * K;

    uint32_t sbase = (uint32_t)__cvta_generic_to_shared(dynsmem);

    float acc[4][4][4];
    #pragma unroll
    for (int mi = 0; mi < 4; mi++)
        #pragma unroll
        for (int ni = 0; ni < 4; ni++)
            #pragma unroll
            for (int e = 0; e < 4; e++) acc[mi][ni][e] = 0.0f;

    const int nk = K / 32;

    auto issue = [&](int chunk, int stage) {
        if (chunk < nk) {
            int kk = chunk * 32;
            const __nv_bfloat16* Ah = A2 + kk;
            const __nv_bfloat16* Al = A2 + K + kk;
            const __nv_bfloat16* Bh = B2 + (size_t)kk * N;
            const __nv_bfloat16* Bl = B2 + (size_t)(K + kk) * N;
            uint32_t st = sbase + stage * STG * 2;
            // A tiles: 128 rows x 4 chunks of 8 halves; 512 cp16 each -> 2/thread
            #pragma unroll
            for (int it = 0; it < 2; it++) {
                int lin = tid + it * 256;
                int m = lin >> 2, c = lin & 3;
                size_t off = (size_t)(bm + m) * lda2 + c * 8;
                uint32_t sm = (m * APAD + c * 8) * 2;
                cp16(st + AH_OFF * 2 + sm, Ah + off, 16);
                cp16(st + AL_OFF * 2 + sm, Al + off, 16);
            }
            // B tiles: 32 rows x 16 chunks of 8 halves; 512 cp16 each -> 2/thread
            #pragma unroll
            for (int it = 0; it < 2; it++) {
                int lin = tid + it * 256;
                int k = lin >> 4, c = lin & 15;
                int col = bn + c * 8;
                int pred = (col + 8 <= N) ? 16 : 0;
                size_t off = (size_t)k * N + col;
                int phys = c ^ (k & 7);
                uint32_t sm = (k * 128 + phys * 8) * 2;
                cp16(st + BH_OFF * 2 + sm, Bh + off, pred);
                cp16(st + BL_OFF * 2 + sm, Bl + off, pred);
            }
        }
        asm volatile("cp.async.commit_group;");   // always commit (empty tail groups)
    };

    issue(0, 0);
    issue(1, 1);

    for (int ch = 0; ch < nk; ch++) {
        int st = ch % NSTAGES;
        asm volatile("cp.async.wait_group %0;" :: "n"(NSTAGES - 2));
        __syncthreads();   // single barrier per chunk: also orders prev reads before overwrite

        issue(ch + NSTAGES - 1, (ch + NSTAGES - 1) % NSTAGES);

        uint32_t stb = sbase + st * STG * 2;
        #pragma unroll
        for (int ks = 0; ks < 2; ks++) {
            int koff = ks * 16 + (lane >> 4) * 8;
            int krow = ks * 16 + (lane & 15);
            int arow = wm * 64 + (lane & 15);

            uint32_t bh[4][2], bl[4][2];
            #pragma unroll
            for (int bt = 0; bt < 2; bt++) {
                int cL = wn * 4 + bt * 2 + (lane >> 4);
                int phys = cL ^ (krow & 7);
                uint32_t r[4];
                ldsm4t(r, stb + BH_OFF * 2 + (krow * 128 + phys * 8) * 2);
                bh[bt * 2][0] = r[0]; bh[bt * 2][1] = r[1];
                bh[bt * 2 + 1][0] = r[2]; bh[bt * 2 + 1][1] = r[3];
                ldsm4t(r, stb + BL_OFF * 2 + (krow * 128 + phys * 8) * 2);
                bl[bt * 2][0] = r[0]; bl[bt * 2][1] = r[1];
                bl[bt * 2 + 1][0] = r[2]; bl[bt * 2 + 1][1] = r[3];
            }

            uint32_t af[4][4];
            #pragma unroll
            for (int mt = 0; mt < 4; mt++)
                ldsm4(af[mt], stb + AH_OFF * 2 + ((arow + mt * 16) * APAD + koff) * 2);
            #pragma unroll
            for (int mt = 0; mt < 4; mt++)
                #pragma unroll
                for (int nt = 0; nt < 4; nt++) {
                    mma16816(acc[mt][nt], af[mt], bh[nt]);   // hi*hi
                    mma16816(acc[mt][nt], af[mt], bl[nt]);   // hi*lo
                }
            #pragma unroll
            for (int mt = 0; mt < 4; mt++)
                ldsm4(af[mt], stb + AL_OFF * 2 + ((arow + mt * 16) * APAD + koff) * 2);
            #pragma unroll
            for (int mt = 0; mt < 4; mt++)
                #pragma unroll
                for (int nt = 0; nt < 4; nt++)
                    mma16816(acc[mt][nt], af[mt], bh[nt]);   // lo*hi
        }
    }

    // ---- store ----
    const int g  = lane >> 2;
    const int q4 = (lane & 3) * 2;
    #pragma unroll
    for (int mi = 0; mi < 4; mi++) {
        int r0 = bm + wm * 64 + mi * 16 + g;
        #pragma unroll
        for (int ni = 0; ni < 4; ni++) {
            int c = bn + wn * 32 + ni * 8 + q4;
            if (c < N) {
                float b0 = bias ? bias[c] : 0.0f;
                float b1 = bias ? bias[c + 1] : 0.0f;
                C[(size_t)r0 * ldc + c]           = acc[mi][ni][0] + b0;
                C[(size_t)r0 * ldc + c + 1]       = acc[mi][ni][1] + b1;
                C[(size_t)(r0 + 8) * ldc + c]     = acc[mi][ni][2] + b0;
                C[(size_t)(r0 + 8) * ldc + c + 1] = acc[mi][ni][3] + b1;
            }
        }
    }
}

// ---------------- RoPE kernels ----------------
__global__ void rope_q_kernel(const float* __restrict__ cosp,
                              const float* __restrict__ sinp)
{
    int idx = blockIdx.x * blockDim.x + threadIdx.x;
    int r = idx & 31;
    int h = (idx >> 5) & 31;
    int i = idx >> 10;
    float* base = &g_q[(size_t)i * QW + h * QKD + NOPE];
    float x0 = base[r];
    float x1 = base[r + 32];
    float c0 = cosp[i * ROPE_D + r];
    float c1 = cosp[i * ROPE_D + 32 + r];
    float s0 = sinp[i * ROPE_D + r];
    float s1 = sinp[i * ROPE_D + 32 + r];
    base[r]      = x0 * c0 - x1 * s0;
    base[r + 32] = x1 * c1 + x0 * s1;
}

__global__ void rope_k_kernel(const float* __restrict__ cosp,
                              const float* __restrict__ sinp)
{
    int idx = blockIdx.x * blockDim.x + threadIdx.x;
    int r = idx & 31;
    int i = idx >> 5;
    const float* base = &g_ckv[(size_t)i * CKV_W + KV_RANK];
    float x0 = base[r];
    float x1 = base[r + 32];
    float c0 = cosp[i * ROPE_D + r];
    float c1 = cosp[i * ROPE_D + 32 + r];
    float s0 = sinp[i * ROPE_D + r];
    float s1 = sinp[i * ROPE_D + 32 + r];
    g_krope[(size_t)i * ROPE_D + r]      = x0 * c0 - x1 * s0;
    g_krope[(size_t)i * ROPE_D + 32 + r] = x1 * c1 + x0 * s1;
}

// ---------------- query-tiled sliding-window attention with sink ----------------
#define QT   16
#define QPAD 196
#define KPAD 196
#define VPAD 132
#define LW   144
__global__ __launch_bounds__(256) void attn_tile_kernel(const float* __restrict__ sinks)
{
    __shared__ float Qs[QT][QPAD];
    __shared__ float Ks[16][KPAD];
    __shared__ float Ls[QT][LW];
    __shared__ float Vs[16][VPAD];

    const int i0    = blockIdx.x * QT;
    const int h     = blockIdx.y;
    const int tid   = threadIdx.x;
    const int jbase = i0 - 127;

    #pragma unroll
    for (int it = 0; it < 3; it++) {
        int lin = tid + it * 256;
        int r   = lin / 48;
        int c4  = (lin % 48) * 4;
        float4 v = *reinterpret_cast<const float4*>(
            &g_q[(size_t)(i0 + r) * QW + h * QKD + c4]);
        *reinterpret_cast<float4*>(&Qs[r][c4]) = v;
    }
    __syncthreads();

    const int q = tid >> 4;
    const int j = tid & 15;

    for (int c = 0; c < 9; c++) {
        #pragma unroll
        for (int it = 0; it < 3; it++) {
            int lin = tid + it * 256;
            int r   = lin / 48;
            int c4  = (lin % 48) * 4;
            int key = jbase + c * 16 + r;
            float4 v = make_float4(0.f, 0.f, 0.f, 0.f);
            if (key >= 0 && key < SEQ) {
                if (c4 < NOPE)
                    v = *reinterpret_cast<const float4*>(
                        &g_kv[(size_t)key * KV_W + h * 256 + c4]);
                else
                    v = *reinterpret_cast<const float4*>(
                        &g_krope[(size_t)key * ROPE_D + (c4 - NOPE)]);
            }
            *reinterpret_cast<float4*>(&Ks[r][c4]) = v;
        }
        __syncthreads();
        float acc = 0.0f;
        #pragma unroll 8
        for (int d = 0; d < QKD; d++) acc = fmaf(Qs[q][d], Ks[j][d], acc);
        Ls[q][c * 16 + j] = acc;
        __syncthreads();
    }

    {
        const int lane = tid & 31;
        const int wrp  = tid >> 5;
        const float snk = sinks[h];
        #pragma unroll
        for (int rr = 0; rr < 2; rr++) {
            int row = wrp + rr * 8;
            float vals[5];
            float m = NEGINF;
            #pragma unroll
            for (int u = 0; u < 5; u++) {
                int t = lane + u * 32;
                float x = NEGINF;
                if (t < 143 && t >= row && t <= row + 127 && (jbase + t) >= 0)
                    x = Ls[row][t] * ATTN_SCALE;
                vals[u] = x;
                m = fmaxf(m, x);
            }
            #pragma unroll
            for (int o = 16; o > 0; o >>= 1) m = fmaxf(m, __shfl_xor_sync(0xFFFFFFFFu, m, o));
            m = fmaxf(m, snk);
            float s = 0.0f;
            #pragma unroll
            for (int u = 0; u < 5; u++) {
                float p = (vals[u] > 0.5f * NEGINF) ? __expf(vals[u] - m) : 0.0f;
                vals[u] = p;
                s += p;
            }
            #pragma unroll
            for (int o = 16; o > 0; o >>= 1) s += __shfl_xor_sync(0xFFFFFFFFu, s, o);
            float inv = 1.0f / (s + __expf(snk - m));
            #pragma unroll
            for (int u = 0; u < 5; u++) {
                int t = lane + u * 32;
                if (t < LW) Ls[row][t] = vals[u] * inv;
            }
        }
    }
    __syncthreads();

    const int dg = tid & 15;
    float oacc[8];
    #pragma unroll
    for (int e = 0; e < 8; e++) oacc[e] = 0.0f;

    for (int c = 0; c < 9; c++) {
        #pragma unroll
        for (int it = 0; it < 2; it++) {
            int lin = tid + it * 256;
            int r   = lin >> 5;
            int c4  = (lin & 31) * 4;
            int key = jbase + c * 16 + r;
            float4 v = make_float4(0.f, 0.f, 0.f, 0.f);
            if (key >= 0 && key < SEQ)
                v = *reinterpret_cast<const float4*>(
                    &g_kv[(size_t)key * KV_W + h * 256 + NOPE + c4]);
            *reinterpret_cast<float4*>(&Vs[r][c4]) = v;
        }
        __syncthreads();
        #pragma unroll
        for (int r = 0; r < 16; r++) {
            float p = Ls[q][c * 16 + r];
            float4 v0 = *reinterpret_cast<float4*>(&Vs[r][dg * 8]);
            float4 v1 = *reinterpret_cast<float4*>(&Vs[r][dg * 8 + 4]);
            oacc[0] = fmaf(p, v0.x, oacc[0]);
            oacc[1] = fmaf(p, v0.y, oacc[1]);
            oacc[2] = fmaf(p, v0.z, oacc[2]);
            oacc[3] = fmaf(p, v0.w, oacc[3]);
            oacc[4] = fmaf(p, v1.x, oacc[4]);
            oacc[5] = fmaf(p, v1.y, oacc[5]);
            oacc[6] = fmaf(p, v1.z, oacc[6]);
            oacc[7] = fmaf(p, v1.w, oacc[7]);
        }
        __syncthreads();
    }

    size_t obase = (size_t)(i0 + q) * AOW + h * VD + dg * 8;
    *reinterpret_cast<float4*>(&g_attn[obase])     = make_float4(oacc[0], oacc[1], oacc[2], oacc[3]);
    *reinterpret_cast<float4*>(&g_attn[obase + 4]) = make_float4(oacc[4], oacc[5], oacc[6], oacc[7]);
}

// ---------------- launch ----------------
extern "C" void kernel_launch(void* const* d_in, const int* in_sizes, int n_in,
                              void* d_out, int out_size)
{
    const float* hidden = (const float*)d_in[0];
    const float* cosp   = (const float*)d_in[1];
    const float* sinp   = (const float*)d_in[2];
    const float* Wq     = (const float*)d_in[3];
    const float* bq     = (const float*)d_in[4];
    const float* Wkva   = (const float*)d_in[5];
    const float* bkva   = (const float*)d_in[6];
    const float* Wkvb   = (const float*)d_in[7];
    const float* Wo     = (const float*)d_in[8];
    const float* bo     = (const float*)d_in[9];
    const float* sinks  = (const float*)d_in[10];
    float* out = (float*)d_out;

    float *q, *ckv, *kv, *attn;
    __nv_bfloat16 *a2, *wq2, *wkva2, *wkvb2, *wo2;
    cudaGetSymbolAddress((void**)&q,     g_q);
    cudaGetSymbolAddress((void**)&ckv,   g_ckv);
    cudaGetSymbolAddress((void**)&kv,    g_kv);
    cudaGetSymbolAddress((void**)&attn,  g_attn);
    cudaGetSymbolAddress((void**)&a2,    g_a2);
    cudaGetSymbolAddress((void**)&wq2,   g_wq2);
    cudaGetSymbolAddress((void**)&wkva2, g_wkva2);
    cudaGetSymbolAddress((void**)&wkvb2, g_wkvb2);
    cudaGetSymbolAddress((void**)&wo2,   g_wo2);

    cudaFuncSetAttribute(gemm_split,
                         cudaFuncAttributeMaxDynamicSharedMemorySize, GEMM_SMEM);

    // ---- weight splits ----
    split_wgt<<<(size_t)HID * QW / 4 / 256, 256>>>(Wq, wq2, (size_t)HID * QW);
    split_wgt<<<(size_t)HID * CKV_W / 4 / 256, 256>>>(Wkva, wkva2, (size_t)HID * CKV_W);
    split_wgt<<<(size_t)KV_RANK * KV_W / 4 / 256, 256>>>(Wkvb, wkvb2, (size_t)KV_RANK * KV_W);
    split_wgt<<<(size_t)AOW * HID / 4 / 256, 256>>>(Wo, wo2, (size_t)AOW * HID);

    // ---- hidden split, Q and KVA projections ----
    split_act<<<SEQ * HID / 4 / 256, 256>>>(hidden, a2, HID, HID);
    gemm_split<<<dim3(QW / 128, SEQ / 128), 256, GEMM_SMEM>>>(
        a2, wq2, bq, q, QW, QW, HID);
    gemm_split<<<dim3((CKV_W + 127) / 128, SEQ / 128), 256, GEMM_SMEM>>>(
        a2, wkva2, bkva, ckv, CKV_W, CKV_W, HID);

    // ---- RoPE ----
    rope_q_kernel<<<(SEQ * NH * 32) / 256, 256>>>(cosp, sinp);
    rope_k_kernel<<<(SEQ * 32) / 256, 256>>>(cosp, sinp);

    // ---- latent split, KV expansion ----
    split_act<<<SEQ * KV_RANK / 4 / 256, 256>>>(ckv, a2, CKV_W, KV_RANK);
    gemm_split<<<dim3(KV_W / 128, SEQ / 128), 256, GEMM_SMEM>>>(
        a2, wkvb2, nullptr, kv, KV_W, KV_W, KV_RANK);

    // ---- attention (query-tiled) ----
    attn_tile_kernel<<<dim3(SEQ / QT, NH), 256>>>(sinks);

    // ---- attn split, output projection ----
    split_act<<<SEQ * AOW / 4 / 256, 256>>>(attn, a2, AOW, AOW);
    gemm_split<<<dim3(HID / 128, SEQ / 128), 256, GEMM_SMEM>>>(
        a2, wo2, bo, out, HID, HID, AOW);
}